// round 6
// baseline (speedup 1.0000x reference)
#include <cuda_runtime.h>
#include <math.h>

#define PHq 7
#define PWq 7
#define CC 256
#define HH 50
#define WW 76
#define SCALE 0.0625f

// One thread per output element: tid = ((n*C + c)*PH + ph)*PW + pw
__global__ void roipool_kernel(const float* __restrict__ feats,
                               const float* __restrict__ rois,
                               float* __restrict__ out,
                               int total) {
    int tid = blockIdx.x * blockDim.x + threadIdx.x;
    if (tid >= total) return;

    int pw = tid % PWq;
    int ph = (tid / PWq) % PHq;
    int c  = (tid / (PWq * PHq)) % CC;
    int n  = tid / (PWq * PHq * CC);

    const float* r = rois + n * 5;
    int b = (int)r[0];

    // round-half-to-even, exact *2^-4 scaling — matches jnp.round(rois*0.0625)
    int x1 = __float2int_rn(r[1] * SCALE);
    int y1 = __float2int_rn(r[2] * SCALE);
    int x2 = __float2int_rn(r[3] * SCALE);
    int y2 = __float2int_rn(r[4] * SCALE);

    float ext_h = (float)max(y2 - y1 + 1, 1);
    float ext_w = (float)max(x2 - x1 + 1, 1);

    // XLA lowers extent/7.0 as extent * fl32(1/7)  (algebraic simplifier:
    // divide-by-constant -> multiply-by-reciprocal). Replicate exactly.
    const float R7 = 1.0f / 7.0f;  // constant-folded, correctly rounded
    float bin_h = __fmul_rn(ext_h, R7);
    float bin_w = __fmul_rn(ext_w, R7);

    int hstart = (int)floorf(__fmul_rn((float)ph, bin_h)) + y1;
    int hend   = (int)ceilf (__fmul_rn((float)(ph + 1), bin_h)) + y1;
    int wstart = (int)floorf(__fmul_rn((float)pw, bin_w)) + x1;
    int wend   = (int)ceilf (__fmul_rn((float)(pw + 1), bin_w)) + x1;

    hstart = min(max(hstart, 0), HH);
    hend   = min(max(hend,   0), HH);
    wstart = min(max(wstart, 0), WW);
    wend   = min(max(wend,   0), WW);

    float m = -INFINITY;
    bool any = false;
    const float* fbase = feats + ((long)b * CC + c) * (HH * WW);
    for (int h = hstart; h < hend; ++h) {
        const float* row = fbase + h * WW;
        for (int w = wstart; w < wend; ++w) {
            float v = __ldg(row + w);
            m = fmaxf(m, v);
            any = true;
        }
    }
    out[tid] = any ? m : 0.0f;
}

extern "C" void kernel_launch(void* const* d_in, const int* in_sizes, int n_in,
                              void* d_out, int out_size) {
    // features = large buffer, rois = small buffer (order-robust)
    int fi = 0, ri = 1;
    if (n_in >= 2 && in_sizes[0] < in_sizes[1]) { fi = 1; ri = 0; }
    const float* feats = (const float*)d_in[fi];
    const float* rois  = (const float*)d_in[ri];
    float* out = (float*)d_out;

    int total = out_size;  // 128*256*7*7 = 1605632
    int threads = 256;
    int blocks = (total + threads - 1) / threads;
    roipool_kernel<<<blocks, threads>>>(feats, rois, out, total);
}

// round 13
// speedup vs baseline: 1.0171x; 1.0171x over previous
#include <cuda_runtime.h>
#include <math.h>

#define PHq 7
#define PWq 7
#define CC 256
#define HH 50
#define WW 76
#define SCALE 0.0625f
#define PER_ROI (CC * PHq * PWq)        // 12544
#define BLOCKS_PER_ROI (PER_ROI / 256)  // 49

__global__ void roipool_kernel(const float* __restrict__ feats,
                               const float* __restrict__ rois,
                               float* __restrict__ out) {
    __shared__ int sh_hs[PHq], sh_he[PHq];
    __shared__ int sh_ws[PWq], sh_we[PWq];
    __shared__ int sh_boff;

    int n   = blockIdx.x / BLOCKS_PER_ROI;
    int blk = blockIdx.x - n * BLOCKS_PER_ROI;
    int t   = threadIdx.x;

    if (t <= PHq + PWq) {
        const float* r = rois + n * 5;
        int b  = (int)r[0];
        // round-half-to-even; *2^-4 is exact — matches jnp.round(rois*0.0625)
        int x1 = __float2int_rn(r[1] * SCALE);
        int y1 = __float2int_rn(r[2] * SCALE);
        int x2 = __float2int_rn(r[3] * SCALE);
        int y2 = __float2int_rn(r[4] * SCALE);

        // XLA lowers extent/7.0 as extent * fl32(1/7); replicate exactly.
        const float R7 = 1.0f / 7.0f;
        float bin_h = __fmul_rn((float)max(y2 - y1 + 1, 1), R7);
        float bin_w = __fmul_rn((float)max(x2 - x1 + 1, 1), R7);

        if (t < PHq) {
            int hs = (int)floorf(__fmul_rn((float)t, bin_h)) + y1;
            int he = (int)ceilf (__fmul_rn((float)(t + 1), bin_h)) + y1;
            sh_hs[t] = min(max(hs, 0), HH);
            sh_he[t] = min(max(he, 0), HH);
        }
        if (t >= PHq && t < PHq + PWq) {
            int u = t - PHq;
            int ws = (int)floorf(__fmul_rn((float)u, bin_w)) + x1;
            int we = (int)ceilf (__fmul_rn((float)(u + 1), bin_w)) + x1;
            sh_ws[u] = min(max(ws, 0), WW);
            sh_we[u] = min(max(we, 0), WW);
        }
        if (t == PHq + PWq) {
            sh_boff = b * (CC * HH * WW);
        }
    }
    __syncthreads();

    int off = blk * 256 + t;          // within-ROI output offset
    int c   = off / 49;
    int bin = off - c * 49;
    int ph  = bin / 7;
    int pw  = bin - ph * 7;

    int hs = sh_hs[ph], he = sh_he[ph];
    int ws = sh_ws[pw], we = sh_we[pw];
    bool nonempty = (he > hs) && (we > ws);

    const float* fbase = feats + sh_boff + c * (HH * WW);
    float m = -INFINITY;
    for (int h = hs; h < he; ++h) {
        const float* row = fbase + h * WW;
        #pragma unroll 4
        for (int w = ws; w < we; ++w) {
            m = fmaxf(m, row[w]);
        }
    }
    out[blockIdx.x * 256 + t] = nonempty ? m : 0.0f;
}

extern "C" void kernel_launch(void* const* d_in, const int* in_sizes, int n_in,
                              void* d_out, int out_size) {
    // features = large buffer, rois = small buffer (order-robust)
    int fi = 0, ri = 1;
    if (n_in >= 2 && in_sizes[0] < in_sizes[1]) { fi = 1; ri = 0; }
    const float* feats = (const float*)d_in[fi];
    const float* rois  = (const float*)d_in[ri];
    float* out = (float*)d_out;

    int blocks = out_size / 256;   // 6272 = 128 ROIs * 49 blocks, exact
    roipool_kernel<<<blocks, 256>>>(feats, rois, out);
}